// round 1
// baseline (speedup 1.0000x reference)
#include <cuda_runtime.h>

// ---------------- problem constants ----------------
#define NS    48          // spatial extent per axis
#define G     12          // windows per axis
#define DIM   256
#define H     8
#define HD    32
#define WIN   64          // tokens per window (4*4*4)
#define NW    1728        // G^3
#define NTOK  110592      // 48^3
#define QKVN  768

// ---------------- scratch (device globals, no allocation) ----------------
__device__ float g_qkv[(size_t)NTOK * QKVN];    // windowed-token order, [t][768] (q|k|v)
__device__ float g_attn[(size_t)NTOK * DIM];    // windowed-token order, [t][h*32+d]

// windowed token t -> linear token index into the (unshifted) x / output tensor.
// Folds the cyclic shift: shifted coordinate X corresponds to source (X+2)%48.
__device__ __forceinline__ int src_token(int t) {
    int win = t >> 6, i = t & 63;
    int a = win / 144, b = (win / 12) % 12, c = win % 12;
    int ix = i >> 4, iy = (i >> 2) & 3, iz = i & 3;
    int X = a * 4 + ix + 2; if (X >= NS) X -= NS;
    int Y = b * 4 + iy + 2; if (Y >= NS) Y -= NS;
    int Z = c * 4 + iz + 2; if (Z >= NS) Z -= NS;
    return (X * NS + Y) * NS + Z;
}

// ---------------- kernel A: rolled-gather QKV GEMM (M=110592, K=256, N=768) ----
// 64x64 tile, BK=16, 256 threads, 4x4 microtile per thread.
__global__ __launch_bounds__(256) void qkv_gemm(const float* __restrict__ X,
                                                const float* __restrict__ Wq) {
    __shared__ float As[16][64];
    __shared__ float Bs[16][64];
    __shared__ int   srcRow[64];

    const int tid = threadIdx.x;
    const int mb  = blockIdx.y * 64;
    const int nb  = blockIdx.x * 64;

    if (tid < 64) srcRow[tid] = src_token(mb + tid);
    __syncthreads();

    const int tx = tid & 15, ty = tid >> 4;
    const int lm = tid >> 2,  lk4 = (tid & 3) * 4;   // A tile load coords
    const int bk = tid >> 4,  bn4 = (tid & 15) * 4;  // B tile load coords

    float acc[4][4] = {};

    for (int k0 = 0; k0 < DIM; k0 += 16) {
        float4 av = *(const float4*)(X  + (size_t)srcRow[lm] * DIM + k0 + lk4);
        float4 bv = *(const float4*)(Wq + (size_t)(k0 + bk) * QKVN + nb + bn4);
        __syncthreads();
        As[lk4 + 0][lm] = av.x; As[lk4 + 1][lm] = av.y;
        As[lk4 + 2][lm] = av.z; As[lk4 + 3][lm] = av.w;
        Bs[bk][bn4 + 0] = bv.x; Bs[bk][bn4 + 1] = bv.y;
        Bs[bk][bn4 + 2] = bv.z; Bs[bk][bn4 + 3] = bv.w;
        __syncthreads();
        #pragma unroll
        for (int k = 0; k < 16; k++) {
            float a[4], b[4];
            #pragma unroll
            for (int i = 0; i < 4; i++) a[i] = As[k][ty * 4 + i];
            #pragma unroll
            for (int j = 0; j < 4; j++) b[j] = Bs[k][tx * 4 + j];
            #pragma unroll
            for (int i = 0; i < 4; i++)
                #pragma unroll
                for (int j = 0; j < 4; j++) acc[i][j] += a[i] * b[j];
        }
    }
    #pragma unroll
    for (int i = 0; i < 4; i++)
        #pragma unroll
        for (int j = 0; j < 4; j++)
            g_qkv[(size_t)(mb + ty * 4 + i) * QKVN + nb + tx * 4 + j] = acc[i][j];
}

// ---------------- kernel B: per-(window,head) 64x64 attention --------------
// Output window (a',b',c') takes scores (q,k) from window (b',c',a') [ref's
// einops-label mismatch], and V from its own window (a',b',c').
__global__ __launch_bounds__(64) void attn_kernel() {
    __shared__ float qs[64][33];
    __shared__ float ks[64][33];
    __shared__ float vs[64][33];

    const int wp = blockIdx.x;         // output window (a',b',c')
    const int h  = blockIdx.y;
    const int ap = wp / 144, bp = (wp / 12) % 12, cp = wp % 12;
    const int wqk = bp * 144 + cp * 12 + ap;   // (a,b,c) = (b',c',a')
    const int i = threadIdx.x;

    const size_t qbase = (size_t)(wqk * 64) * QKVN + h * HD;
    const size_t vbase = (size_t)(wp  * 64) * QKVN + 512 + h * HD;
    for (int idx = i; idx < 64 * HD; idx += 64) {
        int r = idx >> 5, d = idx & 31;
        qs[r][d] = g_qkv[qbase + (size_t)r * QKVN + d];
        ks[r][d] = g_qkv[qbase + (size_t)r * QKVN + 256 + d];
        vs[r][d] = g_qkv[vbase + (size_t)r * QKVN + d];
    }
    __syncthreads();

    // mask bits: x-shift mask iff a==11 i.e. bp==11 (bit5 of i^j),
    //            y-shift iff cp==11 (bit3), z-shift iff ap==11 (bit1)
    const int maskbits = ((bp == 11) << 5) | ((cp == 11) << 3) | ((ap == 11) << 1);
    const float scale = 0.1767766952966369f;   // 32^-0.5

    float q[HD];
    #pragma unroll
    for (int d = 0; d < HD; d++) q[d] = qs[i][d];

    float dots[64];
    float rowmax = -1e30f;
    #pragma unroll 4
    for (int j = 0; j < 64; j++) {
        if ((i ^ j) & maskbits) { dots[j] = -1e30f; continue; }
        float s = 0.f;
        #pragma unroll
        for (int d = 0; d < HD; d++) s += q[d] * ks[j][d];
        s *= scale;
        dots[j] = s;
        rowmax = fmaxf(rowmax, s);
    }
    float sum = 0.f;
    #pragma unroll 4
    for (int j = 0; j < 64; j++) {
        float e = __expf(dots[j] - rowmax);
        dots[j] = e;
        sum += e;
    }
    const float inv = 1.f / sum;

    float out[HD] = {};
    #pragma unroll 4
    for (int j = 0; j < 64; j++) {
        float p = dots[j];
        #pragma unroll
        for (int d = 0; d < HD; d++) out[d] += p * vs[j][d];
    }
    float* orow = g_attn + (size_t)(wp * 64 + i) * DIM + h * HD;
    #pragma unroll
    for (int d = 0; d < HD; d++) orow[d] = out[d] * inv;
}

// ---------------- kernel C: output projection + bias + roll-back scatter ----
// M=110592 (windowed order, contiguous A), K=256, N=256.
__global__ __launch_bounds__(256) void proj_gemm(const float* __restrict__ Wo,
                                                 const float* __restrict__ bias,
                                                 float* __restrict__ out) {
    __shared__ float As[16][64];
    __shared__ float Bs[16][64];
    __shared__ int   dstRow[64];

    const int tid = threadIdx.x;
    const int mb  = blockIdx.y * 64;
    const int nb  = blockIdx.x * 64;

    if (tid < 64) dstRow[tid] = src_token(mb + tid);
    __syncthreads();

    const int tx = tid & 15, ty = tid >> 4;
    const int lm = tid >> 2,  lk4 = (tid & 3) * 4;
    const int bk = tid >> 4,  bn4 = (tid & 15) * 4;

    float acc[4][4] = {};

    for (int k0 = 0; k0 < DIM; k0 += 16) {
        float4 av = *(const float4*)(g_attn + (size_t)(mb + lm) * DIM + k0 + lk4);
        float4 bv = *(const float4*)(Wo + (size_t)(k0 + bk) * DIM + nb + bn4);
        __syncthreads();
        As[lk4 + 0][lm] = av.x; As[lk4 + 1][lm] = av.y;
        As[lk4 + 2][lm] = av.z; As[lk4 + 3][lm] = av.w;
        Bs[bk][bn4 + 0] = bv.x; Bs[bk][bn4 + 1] = bv.y;
        Bs[bk][bn4 + 2] = bv.z; Bs[bk][bn4 + 3] = bv.w;
        __syncthreads();
        #pragma unroll
        for (int k = 0; k < 16; k++) {
            float a[4], b[4];
            #pragma unroll
            for (int i = 0; i < 4; i++) a[i] = As[k][ty * 4 + i];
            #pragma unroll
            for (int j = 0; j < 4; j++) b[j] = Bs[k][tx * 4 + j];
            #pragma unroll
            for (int i = 0; i < 4; i++)
                #pragma unroll
                for (int j = 0; j < 4; j++) acc[i][j] += a[i] * b[j];
        }
    }
    #pragma unroll
    for (int i = 0; i < 4; i++) {
        const size_t rbase = (size_t)dstRow[ty * 4 + i] * DIM + nb;
        #pragma unroll
        for (int j = 0; j < 4; j++)
            out[rbase + tx * 4 + j] = acc[i][j] + bias[nb + tx * 4 + j];
    }
}

// ---------------- launch ----------------
extern "C" void kernel_launch(void* const* d_in, const int* in_sizes, int n_in,
                              void* d_out, int out_size) {
    const float* x     = (const float*)d_in[0];
    const float* w_qkv = (const float*)d_in[1];
    const float* w_out = (const float*)d_in[2];
    const float* b_out = (const float*)d_in[3];
    float* out = (float*)d_out;

    qkv_gemm <<<dim3(QKVN / 64, NTOK / 64), 256>>>(x, w_qkv);
    attn_kernel<<<dim3(NW, H), 64>>>();
    proj_gemm<<<dim3(DIM / 64, NTOK / 64), 256>>>(w_out, b_out, out);
}

// round 2
// speedup vs baseline: 1.2832x; 1.2832x over previous
#include <cuda_runtime.h>

// ---------------- problem constants ----------------
#define NS    48
#define DIM   256
#define H     8
#define HD    32
#define NW    1728
#define NTOK  110592
#define QKVN  768

// GEMM tiling
#define BM 128
#define BN 128
#define BK 16
#define BMP 132
#define BNP 132

// ---------------- scratch ----------------
__device__ float g_qkv[(size_t)NTOK * QKVN];
__device__ float g_attn[(size_t)NTOK * DIM];

__device__ __forceinline__ int src_token(int t) {
    int win = t >> 6, i = t & 63;
    int a = win / 144, b = (win / 12) % 12, c = win % 12;
    int ix = i >> 4, iy = (i >> 2) & 3, iz = i & 3;
    int X = a * 4 + ix + 2; if (X >= NS) X -= NS;
    int Y = b * 4 + iy + 2; if (Y >= NS) Y -= NS;
    int Z = c * 4 + iz + 2; if (Z >= NS) Z -= NS;
    return (X * NS + Y) * NS + Z;
}

__device__ __forceinline__ float f2tf32(float f) {
    unsigned u;
    asm("cvt.rna.tf32.f32 %0, %1;" : "=r"(u) : "f"(f));
    return __uint_as_float(u);
}

__device__ __forceinline__ void mma_tf32(float* d, const unsigned* a, const unsigned* b) {
    asm volatile(
        "mma.sync.aligned.m16n8k8.row.col.f32.tf32.tf32.f32 "
        "{%0,%1,%2,%3},{%4,%5,%6,%7},{%8,%9},{%0,%1,%2,%3};"
        : "+f"(d[0]), "+f"(d[1]), "+f"(d[2]), "+f"(d[3])
        : "r"(a[0]), "r"(a[1]), "r"(a[2]), "r"(a[3]), "r"(b[0]), "r"(b[1]));
}

// ---------------- tf32 3-pass GEMM: QKV (gather rolled rows) -----------------
// M=110592, N=768, K=256.  128x128 tile, 8 warps (2m x 4n), warp tile 64x32.
__global__ __launch_bounds__(256) void qkv_gemm_tc(const float* __restrict__ X,
                                                   const float* __restrict__ Wq) {
    __shared__ float AsHi[BK][BMP], AsLo[BK][BMP];
    __shared__ float BsHi[BK][BNP], BsLo[BK][BNP];
    __shared__ int   srcRow[BM];

    const int tid = threadIdx.x;
    const int mb = blockIdx.y * BM, nb = blockIdx.x * BN;
    if (tid < BM) srcRow[tid] = src_token(mb + tid);
    __syncthreads();

    const int warp = tid >> 5, lane = tid & 31;
    const int wm = (warp >> 2) * 64;   // 0 or 64
    const int wn = (warp & 3) * 32;    // 0..96
    const int l4 = lane & 3, g = lane >> 2;

    const int lm = tid >> 1;           // A: row 0..127
    const int lk = (tid & 1) * 8;      // A: k offset 0/8
    const int bkr = tid >> 4;          // B: k row 0..15
    const int bnc = (tid & 15) * 8;    // B: col group

    float acc[4][4][4] = {};

    for (int k0 = 0; k0 < DIM; k0 += BK) {
        const float* ar = X + (size_t)srcRow[lm] * DIM + k0 + lk;
        float4 a0 = *(const float4*)ar, a1 = *(const float4*)(ar + 4);
        const float* br = Wq + (size_t)(k0 + bkr) * QKVN + nb + bnc;
        float4 b0 = *(const float4*)br, b1 = *(const float4*)(br + 4);
        __syncthreads();
        {
            float av[8] = {a0.x, a0.y, a0.z, a0.w, a1.x, a1.y, a1.z, a1.w};
            #pragma unroll
            for (int i = 0; i < 8; i++) {
                float hi = f2tf32(av[i]);
                AsHi[lk + i][lm] = hi;
                AsLo[lk + i][lm] = f2tf32(av[i] - hi);
            }
            float bv[8] = {b0.x, b0.y, b0.z, b0.w, b1.x, b1.y, b1.z, b1.w};
            #pragma unroll
            for (int i = 0; i < 8; i++) {
                float hi = f2tf32(bv[i]);
                BsHi[bkr][bnc + i] = hi;
                BsLo[bkr][bnc + i] = f2tf32(bv[i] - hi);
            }
        }
        __syncthreads();
        #pragma unroll
        for (int kk = 0; kk < BK; kk += 8) {
            unsigned ahi[4][4], alo[4][4], bhi[4][2], blo[4][2];
            #pragma unroll
            for (int i = 0; i < 4; i++) {
                int m0 = wm + i * 16 + g;
                ahi[i][0] = __float_as_uint(AsHi[kk + l4][m0]);
                ahi[i][1] = __float_as_uint(AsHi[kk + l4][m0 + 8]);
                ahi[i][2] = __float_as_uint(AsHi[kk + l4 + 4][m0]);
                ahi[i][3] = __float_as_uint(AsHi[kk + l4 + 4][m0 + 8]);
                alo[i][0] = __float_as_uint(AsLo[kk + l4][m0]);
                alo[i][1] = __float_as_uint(AsLo[kk + l4][m0 + 8]);
                alo[i][2] = __float_as_uint(AsLo[kk + l4 + 4][m0]);
                alo[i][3] = __float_as_uint(AsLo[kk + l4 + 4][m0 + 8]);
            }
            #pragma unroll
            for (int j = 0; j < 4; j++) {
                int n0 = wn + j * 8 + g;
                bhi[j][0] = __float_as_uint(BsHi[kk + l4][n0]);
                bhi[j][1] = __float_as_uint(BsHi[kk + l4 + 4][n0]);
                blo[j][0] = __float_as_uint(BsLo[kk + l4][n0]);
                blo[j][1] = __float_as_uint(BsLo[kk + l4 + 4][n0]);
            }
            #pragma unroll
            for (int i = 0; i < 4; i++)
                #pragma unroll
                for (int j = 0; j < 4; j++) {
                    mma_tf32(acc[i][j], ahi[i], bhi[j]);
                    mma_tf32(acc[i][j], alo[i], bhi[j]);
                    mma_tf32(acc[i][j], ahi[i], blo[j]);
                }
        }
    }
    #pragma unroll
    for (int i = 0; i < 4; i++)
        #pragma unroll
        for (int j = 0; j < 4; j++) {
            int r0 = mb + wm + i * 16 + g;
            int c  = nb + wn + j * 8 + 2 * l4;
            *(float2*)&g_qkv[(size_t)r0 * QKVN + c]       = make_float2(acc[i][j][0], acc[i][j][1]);
            *(float2*)&g_qkv[(size_t)(r0 + 8) * QKVN + c] = make_float2(acc[i][j][2], acc[i][j][3]);
        }
}

// ---------------- tf32 3-pass GEMM: projection + bias + roll-back scatter ----
// M=110592, N=256, K=256.
__global__ __launch_bounds__(256) void proj_gemm_tc(const float* __restrict__ Wo,
                                                    const float* __restrict__ bias,
                                                    float* __restrict__ out) {
    __shared__ float AsHi[BK][BMP], AsLo[BK][BMP];
    __shared__ float BsHi[BK][BNP], BsLo[BK][BNP];
    __shared__ int   dstRow[BM];

    const int tid = threadIdx.x;
    const int mb = blockIdx.y * BM, nb = blockIdx.x * BN;
    if (tid < BM) dstRow[tid] = src_token(mb + tid);
    __syncthreads();

    const int warp = tid >> 5, lane = tid & 31;
    const int wm = (warp >> 2) * 64;
    const int wn = (warp & 3) * 32;
    const int l4 = lane & 3, g = lane >> 2;

    const int lm = tid >> 1;
    const int lk = (tid & 1) * 8;
    const int bkr = tid >> 4;
    const int bnc = (tid & 15) * 8;

    float acc[4][4][4] = {};

    for (int k0 = 0; k0 < DIM; k0 += BK) {
        const float* ar = g_attn + (size_t)(mb + lm) * DIM + k0 + lk;
        float4 a0 = *(const float4*)ar, a1 = *(const float4*)(ar + 4);
        const float* br = Wo + (size_t)(k0 + bkr) * DIM + nb + bnc;
        float4 b0 = *(const float4*)br, b1 = *(const float4*)(br + 4);
        __syncthreads();
        {
            float av[8] = {a0.x, a0.y, a0.z, a0.w, a1.x, a1.y, a1.z, a1.w};
            #pragma unroll
            for (int i = 0; i < 8; i++) {
                float hi = f2tf32(av[i]);
                AsHi[lk + i][lm] = hi;
                AsLo[lk + i][lm] = f2tf32(av[i] - hi);
            }
            float bv[8] = {b0.x, b0.y, b0.z, b0.w, b1.x, b1.y, b1.z, b1.w};
            #pragma unroll
            for (int i = 0; i < 8; i++) {
                float hi = f2tf32(bv[i]);
                BsHi[bkr][bnc + i] = hi;
                BsLo[bkr][bnc + i] = f2tf32(bv[i] - hi);
            }
        }
        __syncthreads();
        #pragma unroll
        for (int kk = 0; kk < BK; kk += 8) {
            unsigned ahi[4][4], alo[4][4], bhi[4][2], blo[4][2];
            #pragma unroll
            for (int i = 0; i < 4; i++) {
                int m0 = wm + i * 16 + g;
                ahi[i][0] = __float_as_uint(AsHi[kk + l4][m0]);
                ahi[i][1] = __float_as_uint(AsHi[kk + l4][m0 + 8]);
                ahi[i][2] = __float_as_uint(AsHi[kk + l4 + 4][m0]);
                ahi[i][3] = __float_as_uint(AsHi[kk + l4 + 4][m0 + 8]);
                alo[i][0] = __float_as_uint(AsLo[kk + l4][m0]);
                alo[i][1] = __float_as_uint(AsLo[kk + l4][m0 + 8]);
                alo[i][2] = __float_as_uint(AsLo[kk + l4 + 4][m0]);
                alo[i][3] = __float_as_uint(AsLo[kk + l4 + 4][m0 + 8]);
            }
            #pragma unroll
            for (int j = 0; j < 4; j++) {
                int n0 = wn + j * 8 + g;
                bhi[j][0] = __float_as_uint(BsHi[kk + l4][n0]);
                bhi[j][1] = __float_as_uint(BsHi[kk + l4 + 4][n0]);
                blo[j][0] = __float_as_uint(BsLo[kk + l4][n0]);
                blo[j][1] = __float_as_uint(BsLo[kk + l4 + 4][n0]);
            }
            #pragma unroll
            for (int i = 0; i < 4; i++)
                #pragma unroll
                for (int j = 0; j < 4; j++) {
                    mma_tf32(acc[i][j], ahi[i], bhi[j]);
                    mma_tf32(acc[i][j], alo[i], bhi[j]);
                    mma_tf32(acc[i][j], ahi[i], blo[j]);
                }
        }
    }
    #pragma unroll
    for (int i = 0; i < 4; i++)
        #pragma unroll
        for (int j = 0; j < 4; j++) {
            int c = nb + wn + j * 8 + 2 * l4;
            float bx = bias[c], by = bias[c + 1];
            int r0 = dstRow[wm + i * 16 + g];
            int r1 = dstRow[wm + i * 16 + g + 8];
            *(float2*)&out[(size_t)r0 * DIM + c] = make_float2(acc[i][j][0] + bx, acc[i][j][1] + by);
            *(float2*)&out[(size_t)r1 * DIM + c] = make_float2(acc[i][j][2] + bx, acc[i][j][3] + by);
        }
}

// ---------------- per-(window,head) 64x64 attention --------------------------
// Output window (a',b',c') takes scores (q,k) from window (b',c',a'), V from own.
__global__ __launch_bounds__(64) void attn_kernel() {
    __shared__ float ks[64][32];
    __shared__ float vs[64][32];

    const int wp = blockIdx.x;
    const int h  = blockIdx.y;
    const int ap = wp / 144, bp = (wp / 12) % 12, cp = wp % 12;
    const int wqk = bp * 144 + cp * 12 + ap;
    const int i = threadIdx.x;

    const size_t qbase = (size_t)(wqk * 64) * QKVN + h * HD;
    const size_t vbase = (size_t)(wp  * 64) * QKVN + 512 + h * HD;

    // q: each thread its own row, direct from gmem (float4)
    float q[HD];
    {
        const float4* qg = (const float4*)(g_qkv + qbase + (size_t)i * QKVN);
        #pragma unroll
        for (int d4 = 0; d4 < 8; d4++) {
            float4 v = qg[d4];
            q[4 * d4] = v.x; q[4 * d4 + 1] = v.y; q[4 * d4 + 2] = v.z; q[4 * d4 + 3] = v.w;
        }
    }
    for (int idx = i; idx < 64 * HD; idx += 64) {
        int r = idx >> 5, d = idx & 31;
        ks[r][d] = g_qkv[qbase + (size_t)r * QKVN + 256 + d];
        vs[r][d] = g_qkv[vbase + (size_t)r * QKVN + d];
    }
    __syncthreads();

    const int maskbits = ((bp == 11) << 5) | ((cp == 11) << 3) | ((ap == 11) << 1);
    const float scale = 0.1767766952966369f;

    float dots[64];
    float rowmax = -1e30f;
    #pragma unroll 4
    for (int j = 0; j < 64; j++) {
        if ((i ^ j) & maskbits) { dots[j] = -1e30f; continue; }
        const float4* kr = (const float4*)ks[j];       // broadcast across warp
        float s = 0.f;
        #pragma unroll
        for (int d4 = 0; d4 < 8; d4++) {
            float4 kv = kr[d4];
            s += q[4 * d4] * kv.x + q[4 * d4 + 1] * kv.y
               + q[4 * d4 + 2] * kv.z + q[4 * d4 + 3] * kv.w;
        }
        s *= scale;
        dots[j] = s;
        rowmax = fmaxf(rowmax, s);
    }
    float sum = 0.f;
    #pragma unroll 4
    for (int j = 0; j < 64; j++) {
        float e = __expf(dots[j] - rowmax);
        dots[j] = e;
        sum += e;
    }
    const float inv = 1.f / sum;

    float out[HD] = {};
    #pragma unroll 2
    for (int j = 0; j < 64; j++) {
        float p = dots[j];
        const float4* vr = (const float4*)vs[j];       // broadcast
        #pragma unroll
        for (int d4 = 0; d4 < 8; d4++) {
            float4 vv = vr[d4];
            out[4 * d4]     += p * vv.x;
            out[4 * d4 + 1] += p * vv.y;
            out[4 * d4 + 2] += p * vv.z;
            out[4 * d4 + 3] += p * vv.w;
        }
    }
    float* orow = g_attn + (size_t)(wp * 64 + i) * DIM + h * HD;
    #pragma unroll
    for (int d4 = 0; d4 < 8; d4++)
        *(float4*)(orow + 4 * d4) = make_float4(out[4 * d4] * inv, out[4 * d4 + 1] * inv,
                                                out[4 * d4 + 2] * inv, out[4 * d4 + 3] * inv);
}

// ---------------- launch ----------------
extern "C" void kernel_launch(void* const* d_in, const int* in_sizes, int n_in,
                              void* d_out, int out_size) {
    const float* x     = (const float*)d_in[0];
    const float* w_qkv = (const float*)d_in[1];
    const float* w_out = (const float*)d_in[2];
    const float* b_out = (const float*)d_in[3];
    float* out = (float*)d_out;

    qkv_gemm_tc <<<dim3(QKVN / BN, NTOK / BM), 256>>>(x, w_qkv);
    attn_kernel <<<dim3(NW, H), 64>>>();
    proj_gemm_tc<<<dim3(DIM / BN, NTOK / BM), 256>>>(w_out, b_out, out);
}

// round 3
// speedup vs baseline: 1.4216x; 1.1079x over previous
#include <cuda_runtime.h>

// ---------------- problem constants ----------------
#define NS    48
#define DIM   256
#define H     8
#define HD    32
#define NW    1728
#define NTOK  110592
#define QKVN  768

// GEMM tiling
#define BM 128
#define BN 128
#define BK 16
#define BMP 132
#define BNP 132

// ---------------- scratch ----------------
__device__ float g_qkv[(size_t)NTOK * QKVN];
__device__ float g_attn[(size_t)NTOK * DIM];

__device__ __forceinline__ int src_token(int t) {
    int win = t >> 6, i = t & 63;
    int a = win / 144, b = (win / 12) % 12, c = win % 12;
    int ix = i >> 4, iy = (i >> 2) & 3, iz = i & 3;
    int X = a * 4 + ix + 2; if (X >= NS) X -= NS;
    int Y = b * 4 + iy + 2; if (Y >= NS) Y -= NS;
    int Z = c * 4 + iz + 2; if (Z >= NS) Z -= NS;
    return (X * NS + Y) * NS + Z;
}

// split fp32 x into tf32 hi + tf32 lo (x ~= hi + lo), both as raw bit patterns
__device__ __forceinline__ void tf32_split(float x, unsigned& hi, unsigned& lo) {
    unsigned h;
    asm("cvt.rna.tf32.f32 %0, %1;" : "=r"(h) : "f"(x));
    float l = x - __uint_as_float(h);
    unsigned lw;
    asm("cvt.rna.tf32.f32 %0, %1;" : "=r"(lw) : "f"(l));
    hi = h; lo = lw;
}

__device__ __forceinline__ void mma_tf32(float* d, const unsigned* a, const unsigned* b) {
    asm volatile(
        "mma.sync.aligned.m16n8k8.row.col.f32.tf32.tf32.f32 "
        "{%0,%1,%2,%3},{%4,%5,%6,%7},{%8,%9},{%0,%1,%2,%3};"
        : "+f"(d[0]), "+f"(d[1]), "+f"(d[2]), "+f"(d[3])
        : "r"(a[0]), "r"(a[1]), "r"(a[2]), "r"(a[3]), "r"(b[0]), "r"(b[1]));
}

// Shared inner machinery for both GEMMs: fp32 smem tiles, in-register tf32 split,
// 3-product (hi*hi + lo*hi + hi*lo) accumulation.
struct Frag {
    unsigned ahi[4][4], alo[4][4], bhi[4][2], blo[4][2];
};

__device__ __forceinline__ void compute_chunk(
    const float (*As)[BMP], const float (*Bs)[BNP],
    int kk, int wm, int wn, int l4, int g, float acc[4][4][4]) {
    Frag f;
    #pragma unroll
    for (int i = 0; i < 4; i++) {
        int m0 = wm + i * 16 + g;
        tf32_split(As[kk + l4][m0],         f.ahi[i][0], f.alo[i][0]);
        tf32_split(As[kk + l4][m0 + 8],     f.ahi[i][1], f.alo[i][1]);
        tf32_split(As[kk + l4 + 4][m0],     f.ahi[i][2], f.alo[i][2]);
        tf32_split(As[kk + l4 + 4][m0 + 8], f.ahi[i][3], f.alo[i][3]);
    }
    #pragma unroll
    for (int j = 0; j < 4; j++) {
        int n0 = wn + j * 8 + g;
        tf32_split(Bs[kk + l4][n0],     f.bhi[j][0], f.blo[j][0]);
        tf32_split(Bs[kk + l4 + 4][n0], f.bhi[j][1], f.blo[j][1]);
    }
    #pragma unroll
    for (int i = 0; i < 4; i++)
        #pragma unroll
        for (int j = 0; j < 4; j++) {
            mma_tf32(acc[i][j], f.ahi[i], f.bhi[j]);
            mma_tf32(acc[i][j], f.alo[i], f.bhi[j]);
            mma_tf32(acc[i][j], f.ahi[i], f.blo[j]);
        }
}

// ---------------- QKV GEMM: M=110592, N=768, K=256 (gather rolled rows) ------
__global__ __launch_bounds__(256) void qkv_gemm_tc(const float* __restrict__ X,
                                                   const float* __restrict__ Wq) {
    __shared__ float As[BK][BMP];
    __shared__ float Bs[BK][BNP];
    __shared__ int   srcRow[BM];

    const int tid = threadIdx.x;
    const int mb = blockIdx.y * BM, nb = blockIdx.x * BN;
    if (tid < BM) srcRow[tid] = src_token(mb + tid);
    __syncthreads();

    const int warp = tid >> 5, lane = tid & 31;
    const int wm = (warp >> 2) * 64;
    const int wn = (warp & 3) * 32;
    const int l4 = lane & 3, g = lane >> 2;

    const int lm = tid >> 1;           // A row 0..127
    const int lk = (tid & 1) * 8;      // A k offset
    const int bkr = tid >> 4;          // B k row
    const int bnc = (tid & 15) * 8;    // B col group

    float acc[4][4][4] = {};

    for (int k0 = 0; k0 < DIM; k0 += BK) {
        const float* ar = X + (size_t)srcRow[lm] * DIM + k0 + lk;
        float4 a0 = *(const float4*)ar, a1 = *(const float4*)(ar + 4);
        const float* br = Wq + (size_t)(k0 + bkr) * QKVN + nb + bnc;
        float4 b0 = *(const float4*)br, b1 = *(const float4*)(br + 4);
        __syncthreads();
        As[lk + 0][lm] = a0.x; As[lk + 1][lm] = a0.y; As[lk + 2][lm] = a0.z; As[lk + 3][lm] = a0.w;
        As[lk + 4][lm] = a1.x; As[lk + 5][lm] = a1.y; As[lk + 6][lm] = a1.z; As[lk + 7][lm] = a1.w;
        *(float4*)&Bs[bkr][bnc]     = b0;
        *(float4*)&Bs[bkr][bnc + 4] = b1;
        __syncthreads();
        compute_chunk(As, Bs, 0, wm, wn, l4, g, acc);
        compute_chunk(As, Bs, 8, wm, wn, l4, g, acc);
    }
    #pragma unroll
    for (int i = 0; i < 4; i++)
        #pragma unroll
        for (int j = 0; j < 4; j++) {
            int r0 = mb + wm + i * 16 + g;
            int c  = nb + wn + j * 8 + 2 * l4;
            *(float2*)&g_qkv[(size_t)r0 * QKVN + c]       = make_float2(acc[i][j][0], acc[i][j][1]);
            *(float2*)&g_qkv[(size_t)(r0 + 8) * QKVN + c] = make_float2(acc[i][j][2], acc[i][j][3]);
        }
}

// ---------------- projection GEMM + bias + roll-back scatter ------------------
__global__ __launch_bounds__(256) void proj_gemm_tc(const float* __restrict__ Wo,
                                                    const float* __restrict__ bias,
                                                    float* __restrict__ out) {
    __shared__ float As[BK][BMP];
    __shared__ float Bs[BK][BNP];
    __shared__ int   dstRow[BM];

    const int tid = threadIdx.x;
    const int mb = blockIdx.y * BM, nb = blockIdx.x * BN;
    if (tid < BM) dstRow[tid] = src_token(mb + tid);
    __syncthreads();

    const int warp = tid >> 5, lane = tid & 31;
    const int wm = (warp >> 2) * 64;
    const int wn = (warp & 3) * 32;
    const int l4 = lane & 3, g = lane >> 2;

    const int lm = tid >> 1;
    const int lk = (tid & 1) * 8;
    const int bkr = tid >> 4;
    const int bnc = (tid & 15) * 8;

    float acc[4][4][4] = {};

    for (int k0 = 0; k0 < DIM; k0 += BK) {
        const float* ar = g_attn + (size_t)(mb + lm) * DIM + k0 + lk;
        float4 a0 = *(const float4*)ar, a1 = *(const float4*)(ar + 4);
        const float* br = Wo + (size_t)(k0 + bkr) * DIM + nb + bnc;
        float4 b0 = *(const float4*)br, b1 = *(const float4*)(br + 4);
        __syncthreads();
        As[lk + 0][lm] = a0.x; As[lk + 1][lm] = a0.y; As[lk + 2][lm] = a0.z; As[lk + 3][lm] = a0.w;
        As[lk + 4][lm] = a1.x; As[lk + 5][lm] = a1.y; As[lk + 6][lm] = a1.z; As[lk + 7][lm] = a1.w;
        *(float4*)&Bs[bkr][bnc]     = b0;
        *(float4*)&Bs[bkr][bnc + 4] = b1;
        __syncthreads();
        compute_chunk(As, Bs, 0, wm, wn, l4, g, acc);
        compute_chunk(As, Bs, 8, wm, wn, l4, g, acc);
    }
    #pragma unroll
    for (int i = 0; i < 4; i++)
        #pragma unroll
        for (int j = 0; j < 4; j++) {
            int c = nb + wn + j * 8 + 2 * l4;
            float bx = bias[c], by = bias[c + 1];
            int r0 = dstRow[wm + i * 16 + g];
            int r1 = dstRow[wm + i * 16 + g + 8];
            *(float2*)&out[(size_t)r0 * DIM + c] = make_float2(acc[i][j][0] + bx, acc[i][j][1] + by);
            *(float2*)&out[(size_t)r1 * DIM + c] = make_float2(acc[i][j][2] + bx, acc[i][j][3] + by);
        }
}

// ---------------- per-(window,head) 64x64 attention --------------------------
// Output window (a',b',c') takes scores (q,k) from window (b',c',a'), V from own.
__global__ __launch_bounds__(64) void attn_kernel() {
    __shared__ float ks[64][32];
    __shared__ float vs[64][32];

    const int wp = blockIdx.x;
    const int h  = blockIdx.y;
    const int ap = wp / 144, bp = (wp / 12) % 12, cp = wp % 12;
    const int wqk = bp * 144 + cp * 12 + ap;
    const int i = threadIdx.x;

    const size_t qbase = (size_t)(wqk * 64) * QKVN + h * HD;
    const size_t vbase = (size_t)(wp  * 64) * QKVN + 512 + h * HD;

    float q[HD];
    {
        const float4* qg = (const float4*)(g_qkv + qbase + (size_t)i * QKVN);
        #pragma unroll
        for (int d4 = 0; d4 < 8; d4++) {
            float4 v = qg[d4];
            q[4 * d4] = v.x; q[4 * d4 + 1] = v.y; q[4 * d4 + 2] = v.z; q[4 * d4 + 3] = v.w;
        }
    }
    for (int idx = i; idx < 64 * HD; idx += 64) {
        int r = idx >> 5, d = idx & 31;
        ks[r][d] = g_qkv[qbase + (size_t)r * QKVN + 256 + d];
        vs[r][d] = g_qkv[vbase + (size_t)r * QKVN + d];
    }
    __syncthreads();

    const int maskbits = ((bp == 11) << 5) | ((cp == 11) << 3) | ((ap == 11) << 1);
    const float scale = 0.1767766952966369f;

    float dots[64];
    float rowmax = -1e30f;
    #pragma unroll 4
    for (int j = 0; j < 64; j++) {
        if ((i ^ j) & maskbits) { dots[j] = -1e30f; continue; }
        const float4* kr = (const float4*)ks[j];
        float s = 0.f;
        #pragma unroll
        for (int d4 = 0; d4 < 8; d4++) {
            float4 kv = kr[d4];
            s += q[4 * d4] * kv.x + q[4 * d4 + 1] * kv.y
               + q[4 * d4 + 2] * kv.z + q[4 * d4 + 3] * kv.w;
        }
        s *= scale;
        dots[j] = s;
        rowmax = fmaxf(rowmax, s);
    }
    float sum = 0.f;
    #pragma unroll 4
    for (int j = 0; j < 64; j++) {
        float e = __expf(dots[j] - rowmax);
        dots[j] = e;
        sum += e;
    }
    const float inv = 1.f / sum;

    float out[HD] = {};
    #pragma unroll 2
    for (int j = 0; j < 64; j++) {
        float p = dots[j];
        const float4* vr = (const float4*)vs[j];
        #pragma unroll
        for (int d4 = 0; d4 < 8; d4++) {
            float4 vv = vr[d4];
            out[4 * d4]     += p * vv.x;
            out[4 * d4 + 1] += p * vv.y;
            out[4 * d4 + 2] += p * vv.z;
            out[4 * d4 + 3] += p * vv.w;
        }
    }
    float* orow = g_attn + (size_t)(wp * 64 + i) * DIM + h * HD;
    #pragma unroll
    for (int d4 = 0; d4 < 8; d4++)
        *(float4*)(orow + 4 * d4) = make_float4(out[4 * d4] * inv, out[4 * d4 + 1] * inv,
                                                out[4 * d4 + 2] * inv, out[4 * d4 + 3] * inv);
}

// ---------------- launch ----------------
extern "C" void kernel_launch(void* const* d_in, const int* in_sizes, int n_in,
                              void* d_out, int out_size) {
    const float* x     = (const float*)d_in[0];
    const float* w_qkv = (const float*)d_in[1];
    const float* w_out = (const float*)d_in[2];
    const float* b_out = (const float*)d_in[3];
    float* out = (float*)d_out;

    qkv_gemm_tc <<<dim3(QKVN / BN, NTOK / BM), 256>>>(x, w_qkv);
    attn_kernel <<<dim3(NW, H), 64>>>();
    proj_gemm_tc<<<dim3(DIM / BN, NTOK / BM), 256>>>(w_out, b_out, out);
}

// round 5
// speedup vs baseline: 1.7028x; 1.1977x over previous
#include <cuda_runtime.h>
#include <cstdint>

// ---------------- problem constants ----------------
#define NS    48
#define DIM   256
#define H     8
#define HD    32
#define NW    1728
#define NTOK  110592
#define QKVN  768
#define NK    16          // DIM / BK
#define AP    20          // padded smem row length (floats), conflict-free for frag loads

// ---------------- scratch ----------------
__device__ float g_qkv [(size_t)NTOK * QKVN];
__device__ float g_attn[(size_t)NTOK * DIM];
__device__ float g_wqkv_t[(size_t)QKVN * DIM];   // [768][256]
__device__ float g_wout_t[(size_t)DIM * DIM];    // [256][256]

__device__ __forceinline__ int src_token(int t) {
    int win = t >> 6, i = t & 63;
    int a = win / 144, b = (win / 12) % 12, c = win % 12;
    int ix = i >> 4, iy = (i >> 2) & 3, iz = i & 3;
    int X = a * 4 + ix + 2; if (X >= NS) X -= NS;
    int Y = b * 4 + iy + 2; if (Y >= NS) Y -= NS;
    int Z = c * 4 + iz + 2; if (Z >= NS) Z -= NS;
    return (X * NS + Y) * NS + Z;
}

// ---------------- mma.sync tf32 helpers ----------------
__device__ __forceinline__ void tf32_split(float x, unsigned& hi, unsigned& lo) {
    unsigned h;
    asm("cvt.rna.tf32.f32 %0, %1;" : "=r"(h) : "f"(x));
    float l = x - __uint_as_float(h);
    unsigned lw;
    asm("cvt.rna.tf32.f32 %0, %1;" : "=r"(lw) : "f"(l));
    hi = h; lo = lw;
}
__device__ __forceinline__ void mma_tf32(float* d, const unsigned* a, const unsigned* b) {
    asm volatile(
        "mma.sync.aligned.m16n8k8.row.col.f32.tf32.tf32.f32 "
        "{%0,%1,%2,%3},{%4,%5,%6,%7},{%8,%9},{%0,%1,%2,%3};"
        : "+f"(d[0]), "+f"(d[1]), "+f"(d[2]), "+f"(d[3])
        : "r"(a[0]), "r"(a[1]), "r"(a[2]), "r"(a[3]), "r"(b[0]), "r"(b[1]));
}

// ---------------- cp.async ----------------
#define CP_ASYNC16(dst, src) \
    asm volatile("cp.async.ca.shared.global [%0], [%1], 16;" :: "r"(dst), "l"(src) : "memory")
#define CP_COMMIT() asm volatile("cp.async.commit_group;" ::: "memory")
#define CP_WAIT1()  asm volatile("cp.async.wait_group 1;" ::: "memory")

// ---------------- weight transpose prep ----------------
template<bool QKV>
__global__ void transpose_k(const float* __restrict__ W) {
    __shared__ float tile[32][33];
    const int N = QKV ? QKVN : DIM;
    float* Wt = QKV ? g_wqkv_t : g_wout_t;
    int bx = blockIdx.x * 32, by = blockIdx.y * 32;
    #pragma unroll
    for (int i = 0; i < 32; i += 8)
        tile[threadIdx.y + i][threadIdx.x] = W[(size_t)(by + threadIdx.y + i) * N + bx + threadIdx.x];
    __syncthreads();
    #pragma unroll
    for (int i = 0; i < 32; i += 8)
        Wt[(size_t)(bx + threadIdx.y + i) * DIM + by + threadIdx.x] = tile[threadIdx.x][threadIdx.y + i];
}

// ---------------- pipelined tf32 GEMM -----------------------------------------
// D[M, N] = A[M,256] * Bt[N,256]^T, 3xTF32.  128x128 tile, BK=16, 3-stage cp.async.
// smem tiles stored [row][AP] (row = m for A, n for B; col = k within chunk).
__device__ __forceinline__ void compute_chunk_p(
    const float (*As)[AP], const float (*Bs)[AP],
    int kk, int wm, int wn, int l4, int g, float acc[4][4][4]) {
    unsigned ahi[4][4], alo[4][4], bhi[4][2], blo[4][2];
    #pragma unroll
    for (int i = 0; i < 4; i++) {
        int m0 = wm + i * 16 + g;
        tf32_split(As[m0][kk + l4],          ahi[i][0], alo[i][0]);
        tf32_split(As[m0 + 8][kk + l4],      ahi[i][1], alo[i][1]);
        tf32_split(As[m0][kk + l4 + 4],      ahi[i][2], alo[i][2]);
        tf32_split(As[m0 + 8][kk + l4 + 4],  ahi[i][3], alo[i][3]);
    }
    #pragma unroll
    for (int j = 0; j < 4; j++) {
        int n0 = wn + j * 8 + g;
        tf32_split(Bs[n0][kk + l4],         bhi[j][0], blo[j][0]);
        tf32_split(Bs[n0][kk + l4 + 4],     bhi[j][1], blo[j][1]);
    }
    #pragma unroll
    for (int i = 0; i < 4; i++)
        #pragma unroll
        for (int j = 0; j < 4; j++) {
            mma_tf32(acc[i][j], ahi[i], bhi[j]);
            mma_tf32(acc[i][j], alo[i], bhi[j]);
            mma_tf32(acc[i][j], ahi[i], blo[j]);
        }
}

template<int NBLK, bool GATHER_A, bool SCATTER_OUT>
__global__ __launch_bounds__(256, 2) void gemm_tc(
        const float* __restrict__ Aext, const float* __restrict__ bias,
        float* __restrict__ OutExt) {
    extern __shared__ float smem[];
    float (*As)[128][AP] = (float (*)[128][AP])smem;                 // 3 stages
    float (*Bs)[128][AP] = (float (*)[128][AP])(smem + 3 * 128 * AP);

    const int tid = threadIdx.x;
    const int warp = tid >> 5, lane = tid & 31;
    const int g = lane >> 2, l4 = lane & 3;
    const int wm = (warp >> 2) * 64, wn = (warp & 3) * 32;

    const float* Ain = GATHER_A ? Aext : g_attn;
    const float* Bt  = GATHER_A ? g_wqkv_t : g_wout_t;
    float* Out = SCATTER_OUT ? OutExt : g_qkv;
    const int NOUT = NBLK * 128;

    const int mb = blockIdx.y * 128, nb = blockIdx.x * 128;

    // per-thread load coords: 2 threads per row, 8 floats (32B) each
    const int lr = tid >> 1;
    const int lh = (tid & 1) * 8;
    const int aRow = GATHER_A ? src_token(mb + lr) : (mb + lr);
    const float* aptr = Ain + (size_t)aRow * DIM + lh;
    const float* bptr = Bt + (size_t)(nb + lr) * DIM + lh;
    const uint32_t adst = (uint32_t)__cvta_generic_to_shared(&As[0][lr][lh]);
    const uint32_t bdst = (uint32_t)__cvta_generic_to_shared(&Bs[0][lr][lh]);
    const uint32_t stageB = 128 * AP * 4;   // bytes per stage

    float acc[4][4][4] = {};

    // prologue: stages 0,1
    #pragma unroll
    for (int p = 0; p < 2; p++) {
        CP_ASYNC16(adst + p * stageB,      aptr + p * 16);
        CP_ASYNC16(adst + p * stageB + 16, aptr + p * 16 + 4);
        CP_ASYNC16(bdst + p * stageB,      bptr + p * 16);
        CP_ASYNC16(bdst + p * stageB + 16, bptr + p * 16 + 4);
        CP_COMMIT();
    }

    #pragma unroll 1
    for (int kt = 0; kt < NK; kt++) {
        CP_WAIT1();
        __syncthreads();
        if (kt + 2 < NK) {
            const int s = (kt + 2) % 3;
            CP_ASYNC16(adst + s * stageB,      aptr + (kt + 2) * 16);
            CP_ASYNC16(adst + s * stageB + 16, aptr + (kt + 2) * 16 + 4);
            CP_ASYNC16(bdst + s * stageB,      bptr + (kt + 2) * 16);
            CP_ASYNC16(bdst + s * stageB + 16, bptr + (kt + 2) * 16 + 4);
        }
        CP_COMMIT();
        const int s = kt % 3;
        compute_chunk_p(As[s], Bs[s], 0, wm, wn, l4, g, acc);
        compute_chunk_p(As[s], Bs[s], 8, wm, wn, l4, g, acc);
    }

    #pragma unroll
    for (int i = 0; i < 4; i++) {
        const int orow = mb + wm + i * 16 + g;
        const int r0 = SCATTER_OUT ? src_token(orow) : orow;
        const int r1 = SCATTER_OUT ? src_token(orow + 8) : (orow + 8);
        #pragma unroll
        for (int j = 0; j < 4; j++) {
            int c = nb + wn + j * 8 + 2 * l4;
            float bx = 0.f, by = 0.f;
            if (SCATTER_OUT) { bx = bias[c]; by = bias[c + 1]; }
            *(float2*)&Out[(size_t)r0 * NOUT + c] = make_float2(acc[i][j][0] + bx, acc[i][j][1] + by);
            *(float2*)&Out[(size_t)r1 * NOUT + c] = make_float2(acc[i][j][2] + bx, acc[i][j][3] + by);
        }
    }
}

// ---------------- tensor-core attention ---------------------------------------
// Block = (window wp, head h), 128 threads = 4 warps; warp w owns 16-row strip.
// Scores from window (b',c',a') [einops mismatch], V from own window.
__global__ __launch_bounds__(128) void attn_tc() {
    __shared__ float qs[64][36];       // Q [i][d]
    __shared__ float ks[64][36];       // K [j][d]
    __shared__ float vst[32][68];      // V^T [d][j]
    __shared__ float ps[4][16][68];    // P strips [warp][i_local][j]

    const int wp = blockIdx.x, h = blockIdx.y;
    const int ap = wp / 144, bp = (wp / 12) % 12, cp = wp % 12;
    const int wqk = bp * 144 + cp * 12 + ap;
    const int tid = threadIdx.x;
    const int warp = tid >> 5, lane = tid & 31;
    const int g = lane >> 2, l4 = lane & 3;

    // ---- load Q,K (from wqk) and V^T (from wp) ----
    {
        const int r = tid >> 1, half = (tid & 1) * 16;
        const float* qg = g_qkv + (size_t)(wqk * 64 + r) * QKVN + h * HD + half;
        const float* vg = g_qkv + (size_t)(wp * 64 + r) * QKVN + 512 + h * HD + half;
        #pragma unroll
        for (int c = 0; c < 4; c++) {
            float4 qv = *(const float4*)(qg + 4 * c);
            *(float4*)&qs[r][half + 4 * c] = qv;
            float4 kv = *(const float4*)(qg + 256 + 4 * c);
            *(float4*)&ks[r][half + 4 * c] = kv;
            float4 vv = *(const float4*)(vg + 4 * c);
            vst[half + 4 * c + 0][r] = vv.x;
            vst[half + 4 * c + 1][r] = vv.y;
            vst[half + 4 * c + 2][r] = vv.z;
            vst[half + 4 * c + 3][r] = vv.w;
        }
    }
    __syncthreads();

    const int m0 = warp * 16;
    const int maskbits = ((bp == 11) << 5) | ((cp == 11) << 3) | ((ap == 11) << 1);
    const float scale = 0.1767766952966369f;

    // ---- S = Q K^T (strip 16x64), 3xTF32 ----
    float s[8][4] = {};
    #pragma unroll
    for (int kt = 0; kt < 4; kt++) {
        const int k0 = kt * 8;
        unsigned ahi[4], alo[4];
        tf32_split(qs[m0 + g][k0 + l4],         ahi[0], alo[0]);
        tf32_split(qs[m0 + g + 8][k0 + l4],     ahi[1], alo[1]);
        tf32_split(qs[m0 + g][k0 + l4 + 4],     ahi[2], alo[2]);
        tf32_split(qs[m0 + g + 8][k0 + l4 + 4], ahi[3], alo[3]);
        #pragma unroll
        for (int nt = 0; nt < 8; nt++) {
            unsigned bhi[2], blo[2];
            tf32_split(ks[nt * 8 + g][k0 + l4],     bhi[0], blo[0]);
            tf32_split(ks[nt * 8 + g][k0 + l4 + 4], bhi[1], blo[1]);
            mma_tf32(s[nt], ahi, bhi);
            mma_tf32(s[nt], alo, bhi);
            mma_tf32(s[nt], ahi, blo);
        }
    }

    // ---- mask + softmax (rows g and g+8 of strip) ----
    const int i0 = m0 + g, i1 = m0 + g + 8;
    float mx0 = -1e30f, mx1 = -1e30f;
    #pragma unroll
    for (int nt = 0; nt < 8; nt++) {
        const int j0 = nt * 8 + 2 * l4;
        s[nt][0] = ((i0 ^ j0) & maskbits) ? -1e30f : s[nt][0] * scale;
        s[nt][1] = ((i0 ^ (j0 + 1)) & maskbits) ? -1e30f : s[nt][1] * scale;
        s[nt][2] = ((i1 ^ j0) & maskbits) ? -1e30f : s[nt][2] * scale;
        s[nt][3] = ((i1 ^ (j0 + 1)) & maskbits) ? -1e30f : s[nt][3] * scale;
        mx0 = fmaxf(mx0, fmaxf(s[nt][0], s[nt][1]));
        mx1 = fmaxf(mx1, fmaxf(s[nt][2], s[nt][3]));
    }
    mx0 = fmaxf(mx0, __shfl_xor_sync(0xFFFFFFFF, mx0, 1));
    mx0 = fmaxf(mx0, __shfl_xor_sync(0xFFFFFFFF, mx0, 2));
    mx1 = fmaxf(mx1, __shfl_xor_sync(0xFFFFFFFF, mx1, 1));
    mx1 = fmaxf(mx1, __shfl_xor_sync(0xFFFFFFFF, mx1, 2));
    float sm0 = 0.f, sm1 = 0.f;
    #pragma unroll
    for (int nt = 0; nt < 8; nt++) {
        s[nt][0] = __expf(s[nt][0] - mx0);
        s[nt][1] = __expf(s[nt][1] - mx0);
        s[nt][2] = __expf(s[nt][2] - mx1);
        s[nt][3] = __expf(s[nt][3] - mx1);
        sm0 += s[nt][0] + s[nt][1];
        sm1 += s[nt][2] + s[nt][3];
    }
    sm0 += __shfl_xor_sync(0xFFFFFFFF, sm0, 1);
    sm0 += __shfl_xor_sync(0xFFFFFFFF, sm0, 2);
    sm1 += __shfl_xor_sync(0xFFFFFFFF, sm1, 1);
    sm1 += __shfl_xor_sync(0xFFFFFFFF, sm1, 2);
    const float inv0 = 1.f / sm0, inv1 = 1.f / sm1;

    // ---- stage P (unnormalized) in per-warp smem ----
    #pragma unroll
    for (int nt = 0; nt < 8; nt++) {
        const int j0 = nt * 8 + 2 * l4;
        ps[warp][g][j0]         = s[nt][0];
        ps[warp][g][j0 + 1]     = s[nt][1];
        ps[warp][g + 8][j0]     = s[nt][2];
        ps[warp][g + 8][j0 + 1] = s[nt][3];
    }
    __syncwarp();

    // ---- O = P V (strip 16x32), 3xTF32 ----
    float o[4][4] = {};
    #pragma unroll
    for (int kt = 0; kt < 8; kt++) {
        const int j0 = kt * 8;
        unsigned ahi[4], alo[4];
        tf32_split(ps[warp][g][j0 + l4],         ahi[0], alo[0]);
        tf32_split(ps[warp][g + 8][j0 + l4],     ahi[1], alo[1]);
        tf32_split(ps[warp][g][j0 + l4 + 4],     ahi[2], alo[2]);
        tf32_split(ps[warp][g + 8][j0 + l4 + 4], ahi[3], alo[3]);
        #pragma unroll
        for (int dt = 0; dt < 4; dt++) {
            unsigned bhi[2], blo[2];
            tf32_split(vst[dt * 8 + g][j0 + l4],     bhi[0], blo[0]);
            tf32_split(vst[dt * 8 + g][j0 + l4 + 4], bhi[1], blo[1]);
            mma_tf32(o[dt], ahi, bhi);
            mma_tf32(o[dt], alo, bhi);
            mma_tf32(o[dt], ahi, blo);
        }
    }

    // ---- normalize + store ----
    float* out0 = g_attn + (size_t)(wp * 64 + i0) * DIM + h * HD;
    float* out1 = g_attn + (size_t)(wp * 64 + i1) * DIM + h * HD;
    #pragma unroll
    for (int dt = 0; dt < 4; dt++) {
        const int d0 = dt * 8 + 2 * l4;
        *(float2*)(out0 + d0) = make_float2(o[dt][0] * inv0, o[dt][1] * inv0);
        *(float2*)(out1 + d0) = make_float2(o[dt][2] * inv1, o[dt][3] * inv1);
    }
}

// ---------------- launch ----------------
extern "C" void kernel_launch(void* const* d_in, const int* in_sizes, int n_in,
                              void* d_out, int out_size) {
    const float* x     = (const float*)d_in[0];
    const float* w_qkv = (const float*)d_in[1];
    const float* w_out = (const float*)d_in[2];
    const float* b_out = (const float*)d_in[3];
    float* out = (float*)d_out;

    const int smem_sz = 6 * 128 * AP * 4;   // 61440 B
    cudaFuncSetAttribute(gemm_tc<6, true, false>,
                         cudaFuncAttributeMaxDynamicSharedMemorySize, smem_sz);
    cudaFuncSetAttribute(gemm_tc<2, false, true>,
                         cudaFuncAttributeMaxDynamicSharedMemorySize, smem_sz);

    transpose_k<true> <<<dim3(QKVN / 32, DIM / 32), dim3(32, 8)>>>(w_qkv);
    transpose_k<false><<<dim3(DIM / 32,  DIM / 32), dim3(32, 8)>>>(w_out);
    gemm_tc<6, true, false><<<dim3(6, NTOK / 128), 256, smem_sz>>>(x, nullptr, nullptr);
    attn_tc<<<dim3(NW, H), 128>>>();
    gemm_tc<2, false, true><<<dim3(2, NTOK / 128), 256, smem_sz>>>(nullptr, b_out, out);
}